// round 5
// baseline (speedup 1.0000x reference)
#include <cuda_runtime.h>
#include <cstdint>
#include <cstddef>

// Problem constants
#define D   384
#define S   512
#define NB  8
#define NPOS (NB*S)          // 4096
#define DD  (D*D)            // 147456

// ---------------- scratch (device globals; no allocation allowed) ----------
__device__ int   g_count;
__device__ int   g_list[NPOS];
__device__ float g_toff[D];
__device__ float g_base[D];
__device__ __align__(16) float g_tok[NPOS * D];
__device__ __align__(16) float g_dep[NPOS * D];
__device__ __align__(16) float g_u  [NPOS * D];

// ---------------- packed f32x2 helpers (sm_103a) ----------------------------
__device__ __forceinline__ unsigned long long fma2(unsigned long long a,
                                                   unsigned long long b,
                                                   unsigned long long c) {
    unsigned long long r;
    asm("fma.rn.f32x2 %0, %1, %2, %3;" : "=l"(r) : "l"(a), "l"(b), "l"(c));
    return r;
}
__device__ __forceinline__ unsigned long long pack2(float x, float y) {
    unsigned long long r;
    asm("mov.b64 %0, {%1, %2};" : "=l"(r) : "f"(x), "f"(y));
    return r;
}
__device__ __forceinline__ float hadd2(unsigned long long a) {
    float x, y;
    asm("mov.b64 {%0, %1}, %2;" : "=f"(x), "=f"(y) : "l"(a));
    return x + y;
}

// ---------------- K0: scalars -----------------------------------------------
// sumw = sum(Wr), toff = tanh(bc), base = toff*sumw + br; reset list counter.
__global__ void k0_scalars(const float* __restrict__ Wr,
                           const float* __restrict__ bc,
                           const float* __restrict__ br) {
    __shared__ float red[512];
    int t = threadIdx.x;                 // 512 threads
    red[t] = Wr[t];
    __syncthreads();
    for (int ofs = 256; ofs > 0; ofs >>= 1) {
        if (t < ofs) red[t] += red[t + ofs];
        __syncthreads();
    }
    float sumw = red[0];
    if (t < D) {
        float to = tanhf(bc[t]);
        g_toff[t] = to;
        g_base[t] = to * sumw + br[0];
    }
    if (t == 0) g_count = 0;
}

// ---------------- K1: output init + active-position list --------------------
// out[b,s1,:] = base if dep_heads[b,s1]==0 else 0.
// Position (b,s2) is "active" iff dep_heads[b, dep_heads[b,s2]] == 0.
__global__ void k1_init(const int* __restrict__ heads, float* __restrict__ out) {
    int r = blockIdx.x;                  // r = b*S + s1  (also acts as s2 index)
    int t = threadIdx.x;                 // 384 threads
    bool m = (heads[r] == 0);
    out[(size_t)r * D + t] = m ? g_base[t] : 0.0f;
    if (t == 0) {
        int b0 = r & ~(S - 1);           // b*S
        if (heads[b0 + heads[r]] == 0) {
            int idx = atomicAdd(&g_count, 1);
            g_list[idx] = r;
        }
    }
}

// ---------------- K1b: gather tok rows, dep = tanh(tok), zero u -------------
__global__ void k1b_prep(const int* __restrict__ tokens,
                         const float* __restrict__ table) {
    int t = threadIdx.x;                 // 384 threads
    int cnt = g_count;
    for (int i = blockIdx.x; i < cnt; i += gridDim.x) {
        int r = g_list[i];
        int tok_id = tokens[r];
        float v = table[(size_t)tok_id * D + t];
        g_tok[i * D + t] = v;
        g_dep[i * D + t] = tanhf(v);
        g_u  [i * D + t] = 0.0f;
    }
}

// ---------------- K2: bilinear for active positions only --------------------
// u[i][o] = sum_{d,e} tok_i[d] * Wc[o,d,e] * dep_i[e]
// Grid: 768 blocks = (o in [0,384)) x (d-half in {0,1}); 384 threads =
// 4 d-partitions (48 d each) x 96 e-quads (float4 of Wc row, coalesced).
#define T2 384

template <int MC>
__device__ __forceinline__ void run_chunk(const float* __restrict__ Wc,
                                          int o, int half, int c0, int cnt,
                                          unsigned long long* smem_tok2,
                                          float* smem_red) {
    const int t  = threadIdx.x;
    const int p  = t / 96;               // d partition 0..3
    const int q  = t - p * 96;           // e quad 0..95
    const int e0 = 4 * q;
    const int dbase = half * 192;        // this block covers d in [dbase, dbase+192)

    // stage tok for this chunk, duplicated for packed FMA: smem[i*192+dl] = (v,v)
    for (int idx = t; idx < MC * 192; idx += T2) {
        int i  = idx / 192;
        int dl = idx - i * 192;
        float v = 0.0f;
        if (c0 + i < cnt) v = g_tok[(c0 + i) * D + dbase + dl];
        smem_tok2[idx] = pack2(v, v);
    }

    // dep quads in registers (padded positions -> 0 so they contribute nothing)
    unsigned long long dlo[MC], dhi[MC];
#pragma unroll
    for (int i = 0; i < MC; i++) {
        float4 dv = make_float4(0.f, 0.f, 0.f, 0.f);
        if (c0 + i < cnt)
            dv = *reinterpret_cast<const float4*>(&g_dep[(c0 + i) * D + e0]);
        dlo[i] = pack2(dv.x, dv.y);
        dhi[i] = pack2(dv.z, dv.w);
    }
    __syncthreads();

    unsigned long long s2[MC];
#pragma unroll
    for (int i = 0; i < MC; i++) s2[i] = 0ULL;   // packed (0.0f, 0.0f)

    const float* wrow = Wc + (size_t)o * DD + (size_t)(dbase + p * 48) * D + e0;
    const unsigned long long* tokp = smem_tok2 + p * 48;

#pragma unroll 4
    for (int dl = 0; dl < 48; ++dl) {
        float4 wv = *reinterpret_cast<const float4*>(wrow + (size_t)dl * D);
        unsigned long long wlo = pack2(wv.x, wv.y);
        unsigned long long whi = pack2(wv.z, wv.w);
#pragma unroll
        for (int i = 0; i < MC; i++) {
            // q2 = (w0*d0 + w2*d2, w1*d1 + w3*d3) ; dot4 = hadd2(q2)
            unsigned long long q2 = fma2(wlo, dlo[i], fma2(whi, dhi[i], 0ULL));
            s2[i] = fma2(tokp[i * 192 + dl], q2, s2[i]);   // += tok[d] * q2
        }
    }
    __syncthreads();

    // reduce over the 384 threads per position
    const int lane = t & 31, wid = t >> 5;   // 12 warps
#pragma unroll
    for (int i = 0; i < MC; i++) {
        float v = hadd2(s2[i]);
        for (int ofs = 16; ofs; ofs >>= 1)
            v += __shfl_down_sync(0xffffffffu, v, ofs);
        if (lane == 0) smem_red[i * 12 + wid] = v;
    }
    __syncthreads();
    if (t < MC && c0 + t < cnt) {
        float acc = 0.0f;
#pragma unroll
        for (int w = 0; w < 12; w++) acc += smem_red[t * 12 + w];
        atomicAdd(&g_u[(c0 + t) * D + o], acc);   // 2 halves commute exactly
    }
    __syncthreads();
}

__global__ void __launch_bounds__(T2) k2_bilinear(const float* __restrict__ Wc) {
    __shared__ unsigned long long smem_tok2[16 * 192];
    __shared__ float smem_red[16 * 12];
    int o    = blockIdx.x >> 1;
    int half = blockIdx.x & 1;
    int cnt  = g_count;
    int c0 = 0;
    while (cnt - c0 > 16) { run_chunk<16>(Wc, o, half, c0, cnt, smem_tok2, smem_red); c0 += 16; }
    int rem = cnt - c0;
    if      (rem > 12) run_chunk<16>(Wc, o, half, c0, cnt, smem_tok2, smem_red);
    else if (rem > 8 ) run_chunk<12>(Wc, o, half, c0, cnt, smem_tok2, smem_red);
    else if (rem > 4 ) run_chunk<8 >(Wc, o, half, c0, cnt, smem_tok2, smem_red);
    else if (rem > 0 ) run_chunk<4 >(Wc, o, half, c0, cnt, smem_tok2, smem_red);
}

// ---------------- K3: epilogue + scatter ------------------------------------
// contrib[o] = (tanh(u+bc) - toff) * Wr[s2]; out[b, dep_heads[b,s2], :] += contrib
__global__ void k3_scatter(const int* __restrict__ heads,
                           const float* __restrict__ Wr,
                           const float* __restrict__ bc,
                           float* __restrict__ out) {
    int t = threadIdx.x;                 // 384 threads
    int cnt = g_count;
    for (int i = blockIdx.x; i < cnt; i += gridDim.x) {
        int r = g_list[i];
        int h = heads[r];
        float w = Wr[r & (S - 1)];
        int row = (r & ~(S - 1)) + h;
        float u = g_u[i * D + t];
        float ton = tanhf(u + bc[t]);
        float c = (ton - g_toff[t]) * w;
        atomicAdd(&out[(size_t)row * D + t], c);
    }
}

// ---------------- launch -----------------------------------------------------
extern "C" void kernel_launch(void* const* d_in, const int* in_sizes, int n_in,
                              void* d_out, int out_size) {
    const int*   tokens = (const int*)  d_in[0];
    // d_in[1] = dep_types: computed-but-discarded in the reference; unused.
    const int*   heads  = (const int*)  d_in[2];
    const float* table  = (const float*)d_in[3];
    const float* Wc     = (const float*)d_in[4];
    const float* bc     = (const float*)d_in[5];
    const float* Wr     = (const float*)d_in[6];
    const float* br     = (const float*)d_in[7];
    float* out = (float*)d_out;

    k0_scalars<<<1, 512>>>(Wr, bc, br);
    k1_init   <<<NPOS, D>>>(heads, out);
    k1b_prep  <<<32, D>>>(tokens, table);
    k2_bilinear<<<2 * D, T2>>>(Wc);
    k3_scatter<<<64, D>>>(heads, Wr, bc, out);
}